// round 13
// baseline (speedup 1.0000x reference)
#include <cuda_runtime.h>
#include <cuda_bf16.h>
#include <math.h>
#include <stdint.h>
#include <stddef.h>

#define NR 8192
#define KSEL 31
#define WANT_CAND 48
#define CAND_CAP 192
#define STAGE_CAP 2048

// ---------------- scratch ----------------------------------------------------
__device__ float g_h1[(size_t)NR * 512];
__device__ float g_emb[(size_t)NR * 512];
__device__ __align__(16) __nv_bfloat16 g_embB[(size_t)NR * 512];
__device__ __align__(16) __nv_bfloat16 g_S16[(size_t)NR * NR];  // 128 MiB bf16 sims
__device__ float g_adj_fb[(size_t)NR * NR];
__device__ float g_xout_fb[(size_t)NR * 16];
__device__ float g_y0[(size_t)NR * 256];
__device__ float g_x1[(size_t)NR * 256];
__device__ float g_y1[(size_t)NR * 16];
__device__ float g_deg[NR];
__device__ float g_dvec[NR];
__device__ int   g_kcnt[NR];
__device__ int   g_kidx[(size_t)NR * 32];
__device__ float g_kval[(size_t)NR * 32];
__device__ int   g_ncnt[NR];
__device__ int   g_roff[NR + 8];
__device__ int   g_cur[NR];
__device__ int   g_csr_i[(size_t)NR * 64];
__device__ float g_csr_v[(size_t)NR * 64];

// ---------------- utility ----------------------------------------------------
__global__ void zero_f4(float4* p, size_t n4) {
    size_t i = blockIdx.x * (size_t)blockDim.x + threadIdx.x;
    size_t st = (size_t)gridDim.x * blockDim.x;
    float4 z = make_float4(0.f, 0.f, 0.f, 0.f);
    for (; i < n4; i += st) p[i] = z;
}

__global__ void zero_small(float* __restrict__ deg, int* __restrict__ kcnt,
                           int* __restrict__ ncnt) {
    int i = blockIdx.x * blockDim.x + threadIdx.x;
    if (i < NR) { deg[i] = 0.f; kcnt[i] = 0; ncnt[i] = 0; }
}

// ---------------- fp32 SGEMM (NT), register-staged double buffering -----------
// Per-output accumulation: single sequential k-ascending fp32 FMA chain (frozen).
template <bool BIAS, bool RELU>
__global__ __launch_bounds__(256, 2)
void sgemm_nt(const float* __restrict__ A, const float* __restrict__ B,
              const float* __restrict__ bias, float* __restrict__ C,
              int M, int N, int K) {
    const int BM = 128, BN = 128, BK = 16;
    __shared__ float As[2][BK][BM];
    __shared__ float Bs[2][BK][BN];
    int tid = threadIdx.x;
    int bm = blockIdx.y * BM, bn = blockIdx.x * BN;
    int tx = tid & 15, ty = tid >> 4;
    int lr = tid >> 2;
    int lc = (tid & 3) << 2;

    float acc[8][8];
#pragma unroll
    for (int i = 0; i < 8; i++)
#pragma unroll
        for (int j = 0; j < 8; j++) acc[i][j] = 0.f;

    float4 va[2], vb[2];
#pragma unroll
    for (int h = 0; h < 2; h++) {
        int r = lr + h * 64;
        va[h] = *(const float4*)(A + (size_t)(bm + r) * K + lc);
        vb[h] = *(const float4*)(B + (size_t)(bn + r) * K + lc);
    }
#pragma unroll
    for (int h = 0; h < 2; h++) {
        int r = lr + h * 64;
        As[0][lc + 0][r] = va[h].x; As[0][lc + 1][r] = va[h].y;
        As[0][lc + 2][r] = va[h].z; As[0][lc + 3][r] = va[h].w;
        Bs[0][lc + 0][r] = vb[h].x; Bs[0][lc + 1][r] = vb[h].y;
        Bs[0][lc + 2][r] = vb[h].z; Bs[0][lc + 3][r] = vb[h].w;
    }
    __syncthreads();

    int buf = 0;
    for (int k0 = 0; k0 < K; k0 += BK) {
        bool more = (k0 + BK) < K;
        if (more) {
#pragma unroll
            for (int h = 0; h < 2; h++) {
                int r = lr + h * 64;
                va[h] = *(const float4*)(A + (size_t)(bm + r) * K + (k0 + BK + lc));
                vb[h] = *(const float4*)(B + (size_t)(bn + r) * K + (k0 + BK + lc));
            }
        }
#pragma unroll
        for (int kk = 0; kk < BK; kk++) {
            float4 a0 = *(const float4*)&As[buf][kk][ty * 8];
            float4 a1 = *(const float4*)&As[buf][kk][ty * 8 + 4];
            float4 b0 = *(const float4*)&Bs[buf][kk][tx * 8];
            float4 b1 = *(const float4*)&Bs[buf][kk][tx * 8 + 4];
            float a[8] = {a0.x, a0.y, a0.z, a0.w, a1.x, a1.y, a1.z, a1.w};
            float b[8] = {b0.x, b0.y, b0.z, b0.w, b1.x, b1.y, b1.z, b1.w};
#pragma unroll
            for (int i = 0; i < 8; i++)
#pragma unroll
                for (int j = 0; j < 8; j++) acc[i][j] = fmaf(a[i], b[j], acc[i][j]);
        }
        if (more) {
            int nb = buf ^ 1;
#pragma unroll
            for (int h = 0; h < 2; h++) {
                int r = lr + h * 64;
                As[nb][lc + 0][r] = va[h].x; As[nb][lc + 1][r] = va[h].y;
                As[nb][lc + 2][r] = va[h].z; As[nb][lc + 3][r] = va[h].w;
                Bs[nb][lc + 0][r] = vb[h].x; Bs[nb][lc + 1][r] = vb[h].y;
                Bs[nb][lc + 2][r] = vb[h].z; Bs[nb][lc + 3][r] = vb[h].w;
            }
        }
        __syncthreads();
        buf ^= 1;
    }

    float bv[8];
    if (BIAS) {
        float4 t0 = *(const float4*)(bias + bn + tx * 8);
        float4 t1 = *(const float4*)(bias + bn + tx * 8 + 4);
        bv[0] = t0.x; bv[1] = t0.y; bv[2] = t0.z; bv[3] = t0.w;
        bv[4] = t1.x; bv[5] = t1.y; bv[6] = t1.z; bv[7] = t1.w;
    }
#pragma unroll
    for (int i = 0; i < 8; i++) {
        size_t off = (size_t)(bm + ty * 8 + i) * N + bn + tx * 8;
        float v[8];
#pragma unroll
        for (int j = 0; j < 8; j++) {
            float t = acc[i][j];
            if (BIAS) t += bv[j];
            if (RELU) t = fmaxf(t, 0.f);
            v[j] = t;
        }
        *(float4*)(C + off)     = make_float4(v[0], v[1], v[2], v[3]);
        *(float4*)(C + off + 4) = make_float4(v[4], v[5], v[6], v[7]);
    }
}

// ---------------- row L2 normalize + bf16 copy ---------------------------------
__global__ void l2norm_rows_bf16(float* __restrict__ h, __nv_bfloat162* __restrict__ hb) {
    int row = blockIdx.x;
    int tid = threadIdx.x;
    float4* p = (float4*)(h + (size_t)row * 512);
    float4 v = p[tid];
    float ss = v.x * v.x + v.y * v.y + v.z * v.z + v.w * v.w;
#pragma unroll
    for (int o = 16; o; o >>= 1) ss += __shfl_xor_sync(0xFFFFFFFFu, ss, o);
    __shared__ float ws[4];
    if ((tid & 31) == 0) ws[tid >> 5] = ss;
    __syncthreads();
    float tot = ws[0] + ws[1] + ws[2] + ws[3];
    float inv = 1.f / fmaxf(sqrtf(tot), 1e-12f);
    float4 nv = make_float4(v.x * inv, v.y * inv, v.z * inv, v.w * inv);
    p[tid] = nv;
    hb[(size_t)row * 256 + 2 * tid]     = __floats2bfloat162_rn(nv.x, nv.y);
    hb[(size_t)row * 256 + 2 * tid + 1] = __floats2bfloat162_rn(nv.z, nv.w);
}

// ---------------- symmetric bf16 tensor-core GEMM: S16 = E@E^T -----------------
#define LDSM_X4(R0, R1, R2, R3, addr) \
    asm volatile("ldmatrix.sync.aligned.m8n8.x4.shared.b16 {%0,%1,%2,%3},[%4];" \
                 : "=r"(R0), "=r"(R1), "=r"(R2), "=r"(R3) : "r"(addr))

#define MMA_BF16(d, a, b) \
    asm volatile("mma.sync.aligned.m16n8k16.row.col.f32.bf16.bf16.f32 " \
                 "{%0,%1,%2,%3},{%4,%5,%6,%7},{%8,%9},{%0,%1,%2,%3};" \
                 : "+f"(d[0]), "+f"(d[1]), "+f"(d[2]), "+f"(d[3]) \
                 : "r"(a[0]), "r"(a[1]), "r"(a[2]), "r"(a[3]), "r"(b[0]), "r"(b[1]))

__device__ __forceinline__ void cp_async8(uint32_t smem, const void* gptr) {
    asm volatile("cp.async.ca.shared.global [%0], [%1], 8;\n" :: "r"(smem), "l"(gptr));
}
__device__ __forceinline__ void cp_commit() { asm volatile("cp.async.commit_group;\n" ::); }
__device__ __forceinline__ void cp_wait1()  { asm volatile("cp.async.wait_group 1;\n" ::); }

__device__ __forceinline__ void ld_stage(const __nv_bfloat16* __restrict__ E,
                                         int bm, int bn, int k0,
                                         uint32_t sA, uint32_t sB, int tid) {
#pragma unroll
    for (int q = 0; q < 4; q++) {
        int idx = tid + 256 * q;
        int r = idx >> 3;
        int c4 = (idx & 7) << 2;
        cp_async8(sA + (uint32_t)(r * 40 + c4) * 2, E + (size_t)(bm + r) * 512 + k0 + c4);
        cp_async8(sB + (uint32_t)(r * 40 + c4) * 2, E + (size_t)(bn + r) * 512 + k0 + c4);
    }
}

__global__ __launch_bounds__(256, 2)
void gemm_bf16_sym(const __nv_bfloat16* __restrict__ E, __nv_bfloat16* __restrict__ S) {
    __shared__ __align__(16) __nv_bfloat16 smf[20480];

    int bx = blockIdx.x, by = blockIdx.y;
    if (by > bx) return;                      // upper-triangular blocks only
    int tid = threadIdx.x, lane = tid & 31, w = tid >> 5;
    int wm = w & 3, wn = w >> 2;
    int bm = by * 128, bn = bx * 128;

    uint32_t base = (uint32_t)__cvta_generic_to_shared(smf);
    uint32_t baseA[2] = { base, base + 5120u * 2 };
    uint32_t baseB[2] = { base + 10240u * 2, base + 15360u * 2 };

    float acc[2][8][4];
#pragma unroll
    for (int i = 0; i < 2; i++)
#pragma unroll
        for (int j = 0; j < 8; j++)
#pragma unroll
            for (int l = 0; l < 4; l++) acc[i][j][l] = 0.f;

    ld_stage(E, bm, bn, 0, baseA[0], baseB[0], tid);
    cp_commit();

    for (int kt = 0; kt < 16; kt++) {
        if (kt < 15)
            ld_stage(E, bm, bn, (kt + 1) * 32, baseA[(kt + 1) & 1], baseB[(kt + 1) & 1], tid);
        cp_commit();
        cp_wait1();
        __syncthreads();
        int buf = kt & 1;
#pragma unroll
        for (int ks = 0; ks < 32; ks += 16) {
            uint32_t a[2][4];
#pragma unroll
            for (int mt = 0; mt < 2; mt++) {
                int r = wm * 32 + mt * 16 + (lane & 15);
                int kk = ks + ((lane >> 4) << 3);
                LDSM_X4(a[mt][0], a[mt][1], a[mt][2], a[mt][3],
                        baseA[buf] + (uint32_t)(r * 40 + kk) * 2);
            }
            uint32_t b[8][2];
#pragma unroll
            for (int p = 0; p < 4; p++) {
                int g = lane >> 3;
                int r = wn * 64 + p * 16 + ((g & 2) << 2) + (lane & 7);
                int kk = ks + ((g & 1) << 3);
                LDSM_X4(b[2 * p][0], b[2 * p][1], b[2 * p + 1][0], b[2 * p + 1][1],
                        baseB[buf] + (uint32_t)(r * 40 + kk) * 2);
            }
#pragma unroll
            for (int mt = 0; mt < 2; mt++)
#pragma unroll
                for (int nt = 0; nt < 8; nt++) MMA_BF16(acc[mt][nt], a[mt], b[nt]);
        }
        __syncthreads();
    }

    // direct store (rows bm.., cols bn..)
#pragma unroll
    for (int mt = 0; mt < 2; mt++)
#pragma unroll
        for (int nt = 0; nt < 8; nt++) {
            int row = bm + wm * 32 + mt * 16 + (lane >> 2);
            int col = bn + wn * 64 + nt * 8 + ((lane & 3) << 1);
            *(__nv_bfloat162*)(S + (size_t)row * NR + col) =
                __floats2bfloat162_rn(acc[mt][nt][0], acc[mt][nt][1]);
            *(__nv_bfloat162*)(S + (size_t)(row + 8) * NR + col) =
                __floats2bfloat162_rn(acc[mt][nt][2], acc[mt][nt][3]);
        }

    // mirrored store via smem transpose (rows bn.., cols bm..)
    if (bx != by) {
        __syncthreads();
        const int TS = 136;
#pragma unroll
        for (int mt = 0; mt < 2; mt++)
#pragma unroll
            for (int nt = 0; nt < 8; nt++) {
                int r = wm * 32 + mt * 16 + (lane >> 2);
                int c = wn * 64 + nt * 8 + ((lane & 3) << 1);
                smf[(c + 0) * TS + r]     = __float2bfloat16_rn(acc[mt][nt][0]);
                smf[(c + 1) * TS + r]     = __float2bfloat16_rn(acc[mt][nt][1]);
                smf[(c + 0) * TS + r + 8] = __float2bfloat16_rn(acc[mt][nt][2]);
                smf[(c + 1) * TS + r + 8] = __float2bfloat16_rn(acc[mt][nt][3]);
            }
        __syncthreads();
#pragma unroll
        for (int q = 0; q < 8; q++) {
            int i = tid + 256 * q;
            int r2 = i >> 4, c2 = i & 15;
            uint4 v = *(const uint4*)(smf + r2 * TS + c2 * 8);
            *(uint4*)(S + (size_t)(bn + r2) * NR + bm + c2 * 8) = v;
        }
    }
}

// ---------------- top-k: 2-sweep staged radix + sequential rescore -------------
__global__ __launch_bounds__(256)
void topk_cand(const __nv_bfloat16* __restrict__ S, const float* __restrict__ emb,
               int* __restrict__ kcnt, int* __restrict__ kidx, float* __restrict__ kval,
               float* __restrict__ deg, int* __restrict__ ncnt) {
    __shared__ unsigned short keys[NR];       // 16 KB
    __shared__ unsigned whist[8][256];        // 8 KB (1 warp per table)
    __shared__ unsigned suf[256];             // 1 KB
    __shared__ float embrow[512];             // 2 KB
    __shared__ unsigned short stage[STAGE_CAP]; // 4 KB: indices in threshold bucket
    __shared__ int   cidx[CAND_CAP];
    __shared__ float cex[CAND_CAP];
    __shared__ unsigned sB1, sW2, sC1, sB2;
    __shared__ int cCnt, stCnt;

    int row = blockIdx.x, tid = threadIdx.x, wid = tid >> 5;

    // init
    for (int i = tid; i < 2048; i += 256) ((unsigned*)whist)[i] = 0;
    if (tid == 0) { cCnt = 0; stCnt = 0; }
    const float4* er = (const float4*)(emb + (size_t)row * 512);
    if (tid < 128) ((float4*)embrow)[tid] = er[tid];
    __syncthreads();

    // sweep 1: load keys + fused MSB histogram
    const uint32_t* Sr = (const uint32_t*)(S + (size_t)row * NR);
    for (int i = tid; i < NR / 2; i += 256) {
        uint32_t u = Sr[i];
        unsigned short h0 = (unsigned short)(u & 0xFFFFu);
        unsigned short h1 = (unsigned short)(u >> 16);
        unsigned k0 = h0 ^ ((h0 & 0x8000u) ? 0xFFFFu : 0x8000u);
        unsigned k1 = h1 ^ ((h1 & 0x8000u) ? 0xFFFFu : 0x8000u);
        keys[2 * i]     = (unsigned short)k0;
        keys[2 * i + 1] = (unsigned short)k1;
        atomicAdd(&whist[wid][k0 >> 8], 1u);
        atomicAdd(&whist[wid][k1 >> 8], 1u);
    }
    __syncthreads();

    // reduce + suffix-sum; pick MSB bucket b1; sure-count & bucket size
    {
        unsigned s = 0;
#pragma unroll
        for (int wv = 0; wv < 8; wv++) s += whist[wv][tid];
        suf[tid] = s;
    }
    __syncthreads();
#pragma unroll
    for (int off = 1; off < 256; off <<= 1) {
        unsigned add = (tid + off < 256) ? suf[tid + off] : 0u;
        __syncthreads();
        suf[tid] += add;
        __syncthreads();
    }
    {
        unsigned nxt = (tid < 255) ? suf[tid + 1] : 0u;
        if (suf[tid] >= WANT_CAND && nxt < WANT_CAND) {
            sB1 = (unsigned)tid;          // threshold MSB bucket
            sW2 = WANT_CAND - nxt;        // still needed from bucket b1
            sC1 = suf[tid] - nxt;         // bucket b1 population
        }
    }
    __syncthreads();
    unsigned b1 = sB1, want2 = sW2;
    int c1 = (int)sC1;

    // zero hist for low-byte pass
    for (int i = tid; i < 2048; i += 256) ((unsigned*)whist)[i] = 0;
    __syncthreads();

    if (c1 <= STAGE_CAP) {
        // sweep 2: collect sure candidates (>b1) into cidx, b1-members into stage
        for (int i = tid; i < NR; i += 256) {
            unsigned tb = (unsigned)keys[i] >> 8;
            if (tb > b1) {
                int p = atomicAdd(&cCnt, 1);
                if (p < CAND_CAP) cidx[p] = i;
            } else if (tb == b1) {
                int p = atomicAdd(&stCnt, 1);
                stage[p] = (unsigned short)i;
            }
        }
        __syncthreads();
        int c = stCnt;
        // mini low-byte histogram over the c staged members
        for (int s = tid; s < c; s += 256)
            atomicAdd(&whist[wid][(unsigned)keys[stage[s]] & 255u], 1u);
        __syncthreads();
        {
            unsigned s = 0;
#pragma unroll
            for (int wv = 0; wv < 8; wv++) s += whist[wv][tid];
            suf[tid] = s;
        }
        __syncthreads();
#pragma unroll
        for (int off = 1; off < 256; off <<= 1) {
            unsigned add = (tid + off < 256) ? suf[tid + off] : 0u;
            __syncthreads();
            suf[tid] += add;
            __syncthreads();
        }
        {
            unsigned nxt = (tid < 255) ? suf[tid + 1] : 0u;
            if (suf[tid] >= want2 && nxt < want2) sB2 = (unsigned)tid;
        }
        __syncthreads();
        unsigned b2 = sB2;
        // mini gather from stage
        for (int s = tid; s < c; s += 256) {
            int idx = stage[s];
            if (((unsigned)keys[idx] & 255u) >= b2) {
                int p = atomicAdd(&cCnt, 1);
                if (p < CAND_CAP) cidx[p] = idx;
            }
        }
        __syncthreads();
    } else {
        // fallback: classic full pass-2 + full gather (rare)
        for (int i = tid; i < NR; i += 256) {
            unsigned u = keys[i];
            if ((u >> 8) == b1) atomicAdd(&whist[wid][u & 255u], 1u);
        }
        __syncthreads();
        {
            unsigned s = 0;
#pragma unroll
            for (int wv = 0; wv < 8; wv++) s += whist[wv][tid];
            suf[tid] = s;
        }
        __syncthreads();
#pragma unroll
        for (int off = 1; off < 256; off <<= 1) {
            unsigned add = (tid + off < 256) ? suf[tid + off] : 0u;
            __syncthreads();
            suf[tid] += add;
            __syncthreads();
        }
        {
            unsigned nxt = (tid < 255) ? suf[tid + 1] : 0u;
            if (suf[tid] >= want2 && nxt < want2) sB2 = (unsigned)tid;
        }
        __syncthreads();
        unsigned T = (b1 << 8) | sB2;
        for (int i = tid; i < NR; i += 256) {
            if ((unsigned)keys[i] >= T) {
                int p = atomicAdd(&cCnt, 1);
                if (p < CAND_CAP) cidx[p] = i;
            }
        }
        __syncthreads();
    }

    int C = min(cCnt, CAND_CAP);

    // SEQUENTIAL k-ascending fp32 FMA rescore (frozen contract)
    for (int c = tid; c < C; c += 256) {
        int j = cidx[c];
        const float4* ej = (const float4*)(emb + (size_t)j * 512);
        float s = 0.f;
        for (int q = 0; q < 128; q++) {
            float4 a = ej[q];
            s = fmaf(a.x, embrow[4 * q + 0], s);
            s = fmaf(a.y, embrow[4 * q + 1], s);
            s = fmaf(a.z, embrow[4 * q + 2], s);
            s = fmaf(a.w, embrow[4 * q + 3], s);
        }
        cex[c] = s;
    }
    __syncthreads();

    // exact top-31 (jax ties: lower index wins)
    if (tid < C) {
        float v = cex[tid];
        int ji = cidx[tid];
        int beats = 0;
        for (int j2 = 0; j2 < C; j2++) {
            float vj = cex[j2];
            beats += (vj > v) || (vj == v && cidx[j2] < ji);
        }
        if (beats < KSEL && v > 0.f) {
            int s0 = atomicAdd(&kcnt[row], 1);
            kidx[row * 32 + s0] = ji;
            kval[row * 32 + s0] = v;
            atomicAdd(&deg[row], 0.5f * v);
            atomicAdd(&deg[ji], 0.5f * v);
            atomicAdd(&ncnt[row], 1);
            atomicAdd(&ncnt[ji], 1);
        }
    }
}

// ---------------- degree vector ----------------------------------------------
__global__ void make_dvec(const float* __restrict__ deg, float* __restrict__ dvec) {
    int i = blockIdx.x * blockDim.x + threadIdx.x;
    if (i < NR) dvec[i] = 1.f / (sqrtf(deg[i]) + 1e-10f);
}

// ---------------- CSR offsets (single block scan) ------------------------------
__global__ void scan_rows(const int* __restrict__ ncnt, int* __restrict__ roff,
                          int* __restrict__ cur) {
    __shared__ int part[256];
    int t = threadIdx.x;
    int base = t * 32;
    int s = 0;
    for (int i = 0; i < 32; i++) s += ncnt[base + i];
    part[t] = s;
    __syncthreads();
    if (t == 0) {
        int run = 0;
        for (int i = 0; i < 256; i++) { int v = part[i]; part[i] = run; run += v; }
        roff[NR] = run;
    }
    __syncthreads();
    int off = part[t];
    for (int i = 0; i < 32; i++) {
        roff[base + i] = off;
        cur[base + i] = off;
        off += ncnt[base + i];
    }
}

// ---------------- scatter: dense adj (scaled) + symmetric CSR (8 rows/block) ----
__global__ void scatter_adj(const int* __restrict__ kcnt, const int* __restrict__ kidx,
                            const float* __restrict__ kval, const float* __restrict__ dvec,
                            float* __restrict__ adj, int* __restrict__ cur,
                            int* __restrict__ csr_i, float* __restrict__ csr_v) {
    int row = blockIdx.x * 8 + (threadIdx.x >> 5);
    int e = threadIdx.x & 31;
    if (e < kcnt[row]) {
        int j = kidx[row * 32 + e];
        float sc = 0.5f * kval[row * 32 + e] * dvec[row] * dvec[j];
        atomicAdd(&adj[(size_t)row * NR + j], sc);
        atomicAdd(&adj[(size_t)j * NR + row], sc);
        int p = atomicAdd(&cur[row], 1);
        csr_i[p] = j;  csr_v[p] = sc;
        int q = atomicAdd(&cur[j], 1);
        csr_i[q] = row; csr_v[q] = sc;
    }
}

// ---------------- CSR SpMM ------------------------------------------------------
__global__ __launch_bounds__(256)
void spmm_csr_relu256(const int* __restrict__ roff, const int* __restrict__ ci,
                      const float* __restrict__ cv, const float* __restrict__ Y,
                      float* __restrict__ out) {
    __shared__ int   si[128];
    __shared__ float sv[128];
    int row = blockIdx.x, tid = threadIdx.x;
    int b0 = roff[row], b1 = roff[row + 1];
    float acc = 0.f;
    for (int c = b0; c < b1; c += 128) {
        int m = min(128, b1 - c);
        __syncthreads();
        if (tid < m) { si[tid] = ci[c + tid]; sv[tid] = cv[c + tid]; }
        __syncthreads();
        for (int l = 0; l < m; l++)
            acc = fmaf(sv[l], Y[(size_t)si[l] * 256 + tid], acc);
    }
    out[(size_t)row * 256 + tid] = fmaxf(acc, 0.f);
}

__global__ __launch_bounds__(256)
void spmm_csr16(const int* __restrict__ roff, const int* __restrict__ ci,
                const float* __restrict__ cv, const float* __restrict__ Y,
                float* __restrict__ out) {
    __shared__ int   si[128];
    __shared__ float sv[128];
    __shared__ float red[16][17];
    int row = blockIdx.x, tid = threadIdx.x;
    int col = tid & 15, sl = tid >> 4;
    int b0 = roff[row], b1 = roff[row + 1];
    float acc = 0.f;
    for (int c = b0; c < b1; c += 128) {
        int m = min(128, b1 - c);
        __syncthreads();
        if (tid < m) { si[tid] = ci[c + tid]; sv[tid] = cv[c + tid]; }
        __syncthreads();
        for (int l = sl; l < m; l += 16)
            acc = fmaf(sv[l], Y[(size_t)si[l] * 16 + col], acc);
    }
    red[sl][col] = acc;
    __syncthreads();
    if (sl == 0) {
        float s = 0.f;
#pragma unroll
        for (int k = 0; k < 16; k++) s += red[k][col];
        out[(size_t)row * 16 + col] = s;
    }
}

// ---------------- tiny GEMM ------------------------------------------------------
__global__ __launch_bounds__(256)
void gemm_small16(const float* __restrict__ X, const float* __restrict__ W,
                  const float* __restrict__ b, float* __restrict__ out) {
    __shared__ float Ws[16][256];
    int tid = threadIdx.x;
    int col = tid & 15, r = tid >> 4;
    for (int i = tid; i < 16 * 256; i += 256) Ws[i >> 8][i & 255] = W[i];
    __syncthreads();
    int row = blockIdx.x * 16 + r;
    const float* x = X + (size_t)row * 256;
    float acc = b[col];
    for (int k = 0; k < 256; k++) acc = fmaf(x[k], Ws[col][k], acc);
    out[(size_t)row * 16 + col] = acc;
}

// ---------------- launch -----------------------------------------------------------
extern "C" void kernel_launch(void* const* d_in, const int* in_sizes, int n_in,
                              void* d_out, int out_size) {
    (void)in_sizes; (void)n_in;
    const float* features = (const float*)d_in[0];
    const float* x        = (const float*)d_in[1];
    const float* gslW0    = (const float*)d_in[2];
    const float* gslb0    = (const float*)d_in[3];
    const float* gslW1    = (const float*)d_in[4];
    const float* gslb1    = (const float*)d_in[5];
    const float* gcnW0    = (const float*)d_in[6];
    const float* gcnb0    = (const float*)d_in[7];
    const float* gcnW1    = (const float*)d_in[8];
    const float* gcnb1    = (const float*)d_in[9];

    float *ph1, *pemb, *py0, *px1, *py1, *pdeg, *pdvec, *pfb, *pxfb, *pkval, *pcsrv;
    __nv_bfloat16 *pembB, *pS16;
    int *pkcnt, *pkidx, *pncnt, *proff, *pcur, *pcsri;
    cudaGetSymbolAddress((void**)&ph1,   g_h1);
    cudaGetSymbolAddress((void**)&pemb,  g_emb);
    cudaGetSymbolAddress((void**)&pembB, g_embB);
    cudaGetSymbolAddress((void**)&pS16,  g_S16);
    cudaGetSymbolAddress((void**)&py0,   g_y0);
    cudaGetSymbolAddress((void**)&px1,   g_x1);
    cudaGetSymbolAddress((void**)&py1,   g_y1);
    cudaGetSymbolAddress((void**)&pdeg,  g_deg);
    cudaGetSymbolAddress((void**)&pdvec, g_dvec);
    cudaGetSymbolAddress((void**)&pfb,   g_adj_fb);
    cudaGetSymbolAddress((void**)&pxfb,  g_xout_fb);
    cudaGetSymbolAddress((void**)&pkcnt, g_kcnt);
    cudaGetSymbolAddress((void**)&pkidx, g_kidx);
    cudaGetSymbolAddress((void**)&pkval, g_kval);
    cudaGetSymbolAddress((void**)&pncnt, g_ncnt);
    cudaGetSymbolAddress((void**)&proff, g_roff);
    cudaGetSymbolAddress((void**)&pcur,  g_cur);
    cudaGetSymbolAddress((void**)&pcsri, g_csr_i);
    cudaGetSymbolAddress((void**)&pcsrv, g_csr_v);

    const size_t NX = (size_t)NR * 16;
    const size_t NADJ = (size_t)NR * NR;
    float* xOut;
    float* adjOut;
    if ((size_t)out_size >= NX + NADJ) {
        xOut = (float*)d_out;
        adjOut = xOut + NX;
    } else if ((size_t)out_size == NADJ) {
        adjOut = (float*)d_out;
        xOut = pxfb;
    } else {
        xOut = (float*)d_out;
        adjOut = pfb;
    }

    // fork side stream; depends only on eFork (t=0) -> concurrent with MLP GEMMs
    cudaStream_t s2;
    cudaStreamCreateWithFlags(&s2, cudaStreamNonBlocking);
    cudaEvent_t eFork, eJoin;
    cudaEventCreateWithFlags(&eFork, cudaEventDisableTiming);
    cudaEventCreateWithFlags(&eJoin, cudaEventDisableTiming);
    cudaEventRecord(eFork, 0);
    cudaStreamWaitEvent(s2, eFork, 0);

    // issues 1-3: gsl chain
    sgemm_nt<true, true ><<<dim3(4, 64), 256>>>(features, gslW0, gslb0, ph1, NR, 512, 512);
    sgemm_nt<true, false><<<dim3(4, 64), 256>>>(ph1, gslW1, gslb1, pemb, NR, 512, 512);
    l2norm_rows_bf16<<<NR, 128>>>(pemb, (__nv_bfloat162*)pembB);

    // issue 4: S-GEMM (profiled launch)
    gemm_bf16_sym<<<dim3(64, 64), 256>>>(pembB, pS16);

    // side stream: adj zero + GCN input GEMM (independent of gsl chain)
    zero_f4<<<4096, 256, 0, s2>>>((float4*)adjOut, NADJ / 4);
    sgemm_nt<true, false><<<dim3(2, 64), 256, 0, s2>>>(x, gcnW0, gcnb0, py0, NR, 256, 512);
    cudaEventRecord(eJoin, s2);

    // selection chain
    zero_small<<<32, 256>>>(pdeg, pkcnt, pncnt);
    topk_cand<<<NR, 256>>>(pS16, pemb, pkcnt, pkidx, pkval, pdeg, pncnt);
    make_dvec<<<32, 256>>>(pdeg, pdvec);
    scan_rows<<<1, 256>>>(pncnt, proff, pcur);

    // join: scatter needs zeroed adj; spmm needs y0
    cudaStreamWaitEvent(0, eJoin, 0);
    scatter_adj<<<NR / 8, 256>>>(pkcnt, pkidx, pkval, pdvec, adjOut, pcur, pcsri, pcsrv);

    // GCN layers (CSR SpMM)
    spmm_csr_relu256<<<NR, 256>>>(proff, pcsri, pcsrv, py0, px1);
    gemm_small16<<<NR / 16, 256>>>(px1, gcnW1, gcnb1, py1);
    spmm_csr16<<<NR, 256>>>(proff, pcsri, pcsrv, py1, xOut);
}

// round 14
// speedup vs baseline: 1.0272x; 1.0272x over previous
#include <cuda_runtime.h>
#include <cuda_bf16.h>
#include <math.h>
#include <stdint.h>
#include <stddef.h>

#define NR 8192
#define KSEL 31
#define WANT_CAND 48
#define CAND_CAP 256

// ---------------- scratch ----------------------------------------------------
__device__ float g_h1[(size_t)NR * 512];
__device__ float g_emb[(size_t)NR * 512];
__device__ __align__(16) __nv_bfloat16 g_embB[(size_t)NR * 512];
__device__ __align__(16) __nv_bfloat16 g_S16[(size_t)NR * NR];  // 128 MiB bf16 sims
__device__ float g_adj_fb[(size_t)NR * NR];
__device__ float g_xout_fb[(size_t)NR * 16];
__device__ float g_y0[(size_t)NR * 256];
__device__ float g_x1[(size_t)NR * 256];
__device__ float g_y1[(size_t)NR * 16];
__device__ float g_deg[NR];
__device__ float g_dvec[NR];
__device__ int   g_kcnt[NR];
__device__ int   g_kidx[(size_t)NR * 32];
__device__ float g_kval[(size_t)NR * 32];
__device__ int   g_ncnt[NR];
__device__ int   g_roff[NR + 8];
__device__ int   g_cur[NR];
__device__ int   g_csr_i[(size_t)NR * 64];
__device__ float g_csr_v[(size_t)NR * 64];

// ---------------- utility ----------------------------------------------------
__global__ void zero_f4(float4* p, size_t n4) {
    size_t i = blockIdx.x * (size_t)blockDim.x + threadIdx.x;
    size_t st = (size_t)gridDim.x * blockDim.x;
    float4 z = make_float4(0.f, 0.f, 0.f, 0.f);
    for (; i < n4; i += st) p[i] = z;
}

__global__ void zero_small(float* __restrict__ deg, int* __restrict__ kcnt,
                           int* __restrict__ ncnt) {
    int i = blockIdx.x * blockDim.x + threadIdx.x;
    if (i < NR) { deg[i] = 0.f; kcnt[i] = 0; ncnt[i] = 0; }
}

// ---------------- fp32 SGEMM (NT), register-staged double buffering -----------
// Per-output accumulation: single sequential k-ascending fp32 FMA chain (frozen).
template <bool BIAS, bool RELU>
__global__ __launch_bounds__(256, 2)
void sgemm_nt(const float* __restrict__ A, const float* __restrict__ B,
              const float* __restrict__ bias, float* __restrict__ C,
              int M, int N, int K) {
    const int BM = 128, BN = 128, BK = 16;
    __shared__ float As[2][BK][BM];
    __shared__ float Bs[2][BK][BN];
    int tid = threadIdx.x;
    int bm = blockIdx.y * BM, bn = blockIdx.x * BN;
    int tx = tid & 15, ty = tid >> 4;
    int lr = tid >> 2;
    int lc = (tid & 3) << 2;

    float acc[8][8];
#pragma unroll
    for (int i = 0; i < 8; i++)
#pragma unroll
        for (int j = 0; j < 8; j++) acc[i][j] = 0.f;

    float4 va[2], vb[2];
#pragma unroll
    for (int h = 0; h < 2; h++) {
        int r = lr + h * 64;
        va[h] = *(const float4*)(A + (size_t)(bm + r) * K + lc);
        vb[h] = *(const float4*)(B + (size_t)(bn + r) * K + lc);
    }
#pragma unroll
    for (int h = 0; h < 2; h++) {
        int r = lr + h * 64;
        As[0][lc + 0][r] = va[h].x; As[0][lc + 1][r] = va[h].y;
        As[0][lc + 2][r] = va[h].z; As[0][lc + 3][r] = va[h].w;
        Bs[0][lc + 0][r] = vb[h].x; Bs[0][lc + 1][r] = vb[h].y;
        Bs[0][lc + 2][r] = vb[h].z; Bs[0][lc + 3][r] = vb[h].w;
    }
    __syncthreads();

    int buf = 0;
    for (int k0 = 0; k0 < K; k0 += BK) {
        bool more = (k0 + BK) < K;
        if (more) {
#pragma unroll
            for (int h = 0; h < 2; h++) {
                int r = lr + h * 64;
                va[h] = *(const float4*)(A + (size_t)(bm + r) * K + (k0 + BK + lc));
                vb[h] = *(const float4*)(B + (size_t)(bn + r) * K + (k0 + BK + lc));
            }
        }
#pragma unroll
        for (int kk = 0; kk < BK; kk++) {
            float4 a0 = *(const float4*)&As[buf][kk][ty * 8];
            float4 a1 = *(const float4*)&As[buf][kk][ty * 8 + 4];
            float4 b0 = *(const float4*)&Bs[buf][kk][tx * 8];
            float4 b1 = *(const float4*)&Bs[buf][kk][tx * 8 + 4];
            float a[8] = {a0.x, a0.y, a0.z, a0.w, a1.x, a1.y, a1.z, a1.w};
            float b[8] = {b0.x, b0.y, b0.z, b0.w, b1.x, b1.y, b1.z, b1.w};
#pragma unroll
            for (int i = 0; i < 8; i++)
#pragma unroll
                for (int j = 0; j < 8; j++) acc[i][j] = fmaf(a[i], b[j], acc[i][j]);
        }
        if (more) {
            int nb = buf ^ 1;
#pragma unroll
            for (int h = 0; h < 2; h++) {
                int r = lr + h * 64;
                As[nb][lc + 0][r] = va[h].x; As[nb][lc + 1][r] = va[h].y;
                As[nb][lc + 2][r] = va[h].z; As[nb][lc + 3][r] = va[h].w;
                Bs[nb][lc + 0][r] = vb[h].x; Bs[nb][lc + 1][r] = vb[h].y;
                Bs[nb][lc + 2][r] = vb[h].z; Bs[nb][lc + 3][r] = vb[h].w;
            }
        }
        __syncthreads();
        buf ^= 1;
    }

    float bv[8];
    if (BIAS) {
        float4 t0 = *(const float4*)(bias + bn + tx * 8);
        float4 t1 = *(const float4*)(bias + bn + tx * 8 + 4);
        bv[0] = t0.x; bv[1] = t0.y; bv[2] = t0.z; bv[3] = t0.w;
        bv[4] = t1.x; bv[5] = t1.y; bv[6] = t1.z; bv[7] = t1.w;
    }
#pragma unroll
    for (int i = 0; i < 8; i++) {
        size_t off = (size_t)(bm + ty * 8 + i) * N + bn + tx * 8;
        float v[8];
#pragma unroll
        for (int j = 0; j < 8; j++) {
            float t = acc[i][j];
            if (BIAS) t += bv[j];
            if (RELU) t = fmaxf(t, 0.f);
            v[j] = t;
        }
        *(float4*)(C + off)     = make_float4(v[0], v[1], v[2], v[3]);
        *(float4*)(C + off + 4) = make_float4(v[4], v[5], v[6], v[7]);
    }
}

// ---------------- row L2 normalize + bf16 copy ---------------------------------
__global__ void l2norm_rows_bf16(float* __restrict__ h, __nv_bfloat162* __restrict__ hb) {
    int row = blockIdx.x;
    int tid = threadIdx.x;
    float4* p = (float4*)(h + (size_t)row * 512);
    float4 v = p[tid];
    float ss = v.x * v.x + v.y * v.y + v.z * v.z + v.w * v.w;
#pragma unroll
    for (int o = 16; o; o >>= 1) ss += __shfl_xor_sync(0xFFFFFFFFu, ss, o);
    __shared__ float ws[4];
    if ((tid & 31) == 0) ws[tid >> 5] = ss;
    __syncthreads();
    float tot = ws[0] + ws[1] + ws[2] + ws[3];
    float inv = 1.f / fmaxf(sqrtf(tot), 1e-12f);
    float4 nv = make_float4(v.x * inv, v.y * inv, v.z * inv, v.w * inv);
    p[tid] = nv;
    hb[(size_t)row * 256 + 2 * tid]     = __floats2bfloat162_rn(nv.x, nv.y);
    hb[(size_t)row * 256 + 2 * tid + 1] = __floats2bfloat162_rn(nv.z, nv.w);
}

// ---------------- symmetric bf16 tensor-core GEMM: S16 = E@E^T -----------------
#define LDSM_X4(R0, R1, R2, R3, addr) \
    asm volatile("ldmatrix.sync.aligned.m8n8.x4.shared.b16 {%0,%1,%2,%3},[%4];" \
                 : "=r"(R0), "=r"(R1), "=r"(R2), "=r"(R3) : "r"(addr))

#define MMA_BF16(d, a, b) \
    asm volatile("mma.sync.aligned.m16n8k16.row.col.f32.bf16.bf16.f32 " \
                 "{%0,%1,%2,%3},{%4,%5,%6,%7},{%8,%9},{%0,%1,%2,%3};" \
                 : "+f"(d[0]), "+f"(d[1]), "+f"(d[2]), "+f"(d[3]) \
                 : "r"(a[0]), "r"(a[1]), "r"(a[2]), "r"(a[3]), "r"(b[0]), "r"(b[1]))

__device__ __forceinline__ void cp_async8(uint32_t smem, const void* gptr) {
    asm volatile("cp.async.ca.shared.global [%0], [%1], 8;\n" :: "r"(smem), "l"(gptr));
}
__device__ __forceinline__ void cp_commit() { asm volatile("cp.async.commit_group;\n" ::); }
__device__ __forceinline__ void cp_wait1()  { asm volatile("cp.async.wait_group 1;\n" ::); }

__device__ __forceinline__ void ld_stage(const __nv_bfloat16* __restrict__ E,
                                         int bm, int bn, int k0,
                                         uint32_t sA, uint32_t sB, int tid) {
#pragma unroll
    for (int q = 0; q < 4; q++) {
        int idx = tid + 256 * q;
        int r = idx >> 3;
        int c4 = (idx & 7) << 2;
        cp_async8(sA + (uint32_t)(r * 40 + c4) * 2, E + (size_t)(bm + r) * 512 + k0 + c4);
        cp_async8(sB + (uint32_t)(r * 40 + c4) * 2, E + (size_t)(bn + r) * 512 + k0 + c4);
    }
}

__global__ __launch_bounds__(256, 2)
void gemm_bf16_sym(const __nv_bfloat16* __restrict__ E, __nv_bfloat16* __restrict__ S) {
    __shared__ __align__(16) __nv_bfloat16 smf[20480];

    int bx = blockIdx.x, by = blockIdx.y;
    if (by > bx) return;                      // upper-triangular blocks only
    int tid = threadIdx.x, lane = tid & 31, w = tid >> 5;
    int wm = w & 3, wn = w >> 2;
    int bm = by * 128, bn = bx * 128;

    uint32_t base = (uint32_t)__cvta_generic_to_shared(smf);
    uint32_t baseA[2] = { base, base + 5120u * 2 };
    uint32_t baseB[2] = { base + 10240u * 2, base + 15360u * 2 };

    float acc[2][8][4];
#pragma unroll
    for (int i = 0; i < 2; i++)
#pragma unroll
        for (int j = 0; j < 8; j++)
#pragma unroll
            for (int l = 0; l < 4; l++) acc[i][j][l] = 0.f;

    ld_stage(E, bm, bn, 0, baseA[0], baseB[0], tid);
    cp_commit();

    for (int kt = 0; kt < 16; kt++) {
        if (kt < 15)
            ld_stage(E, bm, bn, (kt + 1) * 32, baseA[(kt + 1) & 1], baseB[(kt + 1) & 1], tid);
        cp_commit();
        cp_wait1();
        __syncthreads();
        int buf = kt & 1;
#pragma unroll
        for (int ks = 0; ks < 32; ks += 16) {
            uint32_t a[2][4];
#pragma unroll
            for (int mt = 0; mt < 2; mt++) {
                int r = wm * 32 + mt * 16 + (lane & 15);
                int kk = ks + ((lane >> 4) << 3);
                LDSM_X4(a[mt][0], a[mt][1], a[mt][2], a[mt][3],
                        baseA[buf] + (uint32_t)(r * 40 + kk) * 2);
            }
            uint32_t b[8][2];
#pragma unroll
            for (int p = 0; p < 4; p++) {
                int g = lane >> 3;
                int r = wn * 64 + p * 16 + ((g & 2) << 2) + (lane & 7);
                int kk = ks + ((g & 1) << 3);
                LDSM_X4(b[2 * p][0], b[2 * p][1], b[2 * p + 1][0], b[2 * p + 1][1],
                        baseB[buf] + (uint32_t)(r * 40 + kk) * 2);
            }
#pragma unroll
            for (int mt = 0; mt < 2; mt++)
#pragma unroll
                for (int nt = 0; nt < 8; nt++) MMA_BF16(acc[mt][nt], a[mt], b[nt]);
        }
        __syncthreads();
    }

    // direct store (rows bm.., cols bn..)
#pragma unroll
    for (int mt = 0; mt < 2; mt++)
#pragma unroll
        for (int nt = 0; nt < 8; nt++) {
            int row = bm + wm * 32 + mt * 16 + (lane >> 2);
            int col = bn + wn * 64 + nt * 8 + ((lane & 3) << 1);
            *(__nv_bfloat162*)(S + (size_t)row * NR + col) =
                __floats2bfloat162_rn(acc[mt][nt][0], acc[mt][nt][1]);
            *(__nv_bfloat162*)(S + (size_t)(row + 8) * NR + col) =
                __floats2bfloat162_rn(acc[mt][nt][2], acc[mt][nt][3]);
        }

    // mirrored store via smem transpose (rows bn.., cols bm..)
    if (bx != by) {
        __syncthreads();
        const int TS = 136;
#pragma unroll
        for (int mt = 0; mt < 2; mt++)
#pragma unroll
            for (int nt = 0; nt < 8; nt++) {
                int r = wm * 32 + mt * 16 + (lane >> 2);
                int c = wn * 64 + nt * 8 + ((lane & 3) << 1);
                smf[(c + 0) * TS + r]     = __float2bfloat16_rn(acc[mt][nt][0]);
                smf[(c + 1) * TS + r]     = __float2bfloat16_rn(acc[mt][nt][1]);
                smf[(c + 0) * TS + r + 8] = __float2bfloat16_rn(acc[mt][nt][2]);
                smf[(c + 1) * TS + r + 8] = __float2bfloat16_rn(acc[mt][nt][3]);
            }
        __syncthreads();
#pragma unroll
        for (int q = 0; q < 8; q++) {
            int i = tid + 256 * q;
            int r2 = i >> 4, c2 = i & 15;
            uint4 v = *(const uint4*)(smf + r2 * TS + c2 * 8);
            *(uint4*)(S + (size_t)(bn + r2) * NR + bm + c2 * 8) = v;
        }
    }
}

// ---------------- top-k: order-statistic threshold (no histogram) --------------
// T = 48th largest of the 256 per-thread maxima. Provably T <= 48th largest key
// (else >=48 threads each hold a key above it -> contradiction), so {key >= T}
// is a superset of the bf16 top-48. Expected |set| ~ 48 by quantile calibration.
// Fallback to exact 2-pass radix if the set overflows CAND_CAP (rare).
__global__ __launch_bounds__(256)
void topk_cand(const __nv_bfloat16* __restrict__ S, const float* __restrict__ emb,
               int* __restrict__ kcnt, int* __restrict__ kidx, float* __restrict__ kval,
               float* __restrict__ deg, int* __restrict__ ncnt) {
    __shared__ unsigned short keys[NR];      // 16 KB
    __shared__ unsigned short lmax[256];     // per-thread maxima
    __shared__ unsigned whist[8][256];       // fallback hist (8 KB)
    __shared__ unsigned suf[256];
    __shared__ float embrow[512];            // 2 KB
    __shared__ int   cidx[CAND_CAP];
    __shared__ float cex[CAND_CAP];
    __shared__ unsigned sT, sSel, sWant;
    __shared__ int cCnt;

    int row = blockIdx.x, tid = threadIdx.x, wid = tid >> 5;

    // sweep 1: load keys + per-thread max (no atomics)
    const uint32_t* Sr = (const uint32_t*)(S + (size_t)row * NR);
    unsigned lm = 0;
    for (int i = tid; i < NR / 2; i += 256) {
        uint32_t u = Sr[i];
        unsigned short h0 = (unsigned short)(u & 0xFFFFu);
        unsigned short h1 = (unsigned short)(u >> 16);
        unsigned k0 = h0 ^ ((h0 & 0x8000u) ? 0xFFFFu : 0x8000u);
        unsigned k1 = h1 ^ ((h1 & 0x8000u) ? 0xFFFFu : 0x8000u);
        keys[2 * i]     = (unsigned short)k0;
        keys[2 * i + 1] = (unsigned short)k1;
        unsigned m01 = k0 > k1 ? k0 : k1;
        if (m01 > lm) lm = m01;
    }
    lmax[tid] = (unsigned short)lm;
    const float4* er = (const float4*)(emb + (size_t)row * 512);
    if (tid < 128) ((float4*)embrow)[tid] = er[tid];
    if (tid == 0) cCnt = 0;
    __syncthreads();

    // rank-47 (0-indexed) of the 256 local maxima = conservative threshold
    {
        unsigned mv = lmax[tid];
        int rank = 0;
#pragma unroll 8
        for (int j = 0; j < 256; j++) {
            unsigned vj = lmax[j];
            rank += (vj > mv) || (vj == mv && j < tid);
        }
        if (rank == WANT_CAND - 1) sT = mv;
    }
    __syncthreads();
    unsigned T = sT;

    // sweep 2: collect candidates >= T
    for (int i = tid; i < NR; i += 256) {
        if ((unsigned)keys[i] >= T) {
            int p = atomicAdd(&cCnt, 1);
            if (p < CAND_CAP) cidx[p] = i;
        }
    }
    __syncthreads();

    if (cCnt > CAND_CAP) {
        // ---- fallback: exact 2-pass radix threshold (R12-proven), recollect ----
        if (tid == 0) cCnt = 0;
        unsigned prefix = 0, pmask = 0, want = WANT_CAND;
#pragma unroll
        for (int pass = 1; pass >= 0; pass--) {
            for (int i = tid; i < 2048; i += 256) ((unsigned*)whist)[i] = 0;
            __syncthreads();
            int shift = pass * 8;
            for (int i = tid; i < NR; i += 256) {
                unsigned u = keys[i];
                if ((u & pmask) == prefix)
                    atomicAdd(&whist[wid][(u >> shift) & 255], 1u);
            }
            __syncthreads();
            unsigned s = 0;
#pragma unroll
            for (int wv = 0; wv < 8; wv++) s += whist[wv][tid];
            suf[tid] = s;
            __syncthreads();
#pragma unroll
            for (int off = 1; off < 256; off <<= 1) {
                unsigned add = (tid + off < 256) ? suf[tid + off] : 0u;
                __syncthreads();
                suf[tid] += add;
                __syncthreads();
            }
            {
                unsigned nxt = (tid < 255) ? suf[tid + 1] : 0u;
                if (suf[tid] >= want && nxt < want) {
                    sSel = (unsigned)tid;
                    sWant = want - nxt;
                }
            }
            __syncthreads();
            prefix |= sSel << shift;
            pmask |= 0xFFu << shift;
            want = sWant;
            __syncthreads();
        }
        unsigned T2 = prefix;
        for (int i = tid; i < NR; i += 256) {
            if ((unsigned)keys[i] >= T2) {
                int p = atomicAdd(&cCnt, 1);
                if (p < CAND_CAP) cidx[p] = i;
            }
        }
        __syncthreads();
    }

    int C = min(cCnt, CAND_CAP);

    // SEQUENTIAL k-ascending fp32 FMA rescore (frozen contract)
    for (int c = tid; c < C; c += 256) {
        int j = cidx[c];
        const float4* ej = (const float4*)(emb + (size_t)j * 512);
        float s = 0.f;
        for (int q = 0; q < 128; q++) {
            float4 a = ej[q];
            s = fmaf(a.x, embrow[4 * q + 0], s);
            s = fmaf(a.y, embrow[4 * q + 1], s);
            s = fmaf(a.z, embrow[4 * q + 2], s);
            s = fmaf(a.w, embrow[4 * q + 3], s);
        }
        cex[c] = s;
    }
    __syncthreads();

    // exact top-31 (jax ties: lower index wins)
    if (tid < C) {
        float v = cex[tid];
        int ji = cidx[tid];
        int beats = 0;
        for (int j2 = 0; j2 < C; j2++) {
            float vj = cex[j2];
            beats += (vj > v) || (vj == v && cidx[j2] < ji);
        }
        if (beats < KSEL && v > 0.f) {
            int s0 = atomicAdd(&kcnt[row], 1);
            kidx[row * 32 + s0] = ji;
            kval[row * 32 + s0] = v;
            atomicAdd(&deg[row], 0.5f * v);
            atomicAdd(&deg[ji], 0.5f * v);
            atomicAdd(&ncnt[row], 1);
            atomicAdd(&ncnt[ji], 1);
        }
    }
}

// ---------------- degree vector ----------------------------------------------
__global__ void make_dvec(const float* __restrict__ deg, float* __restrict__ dvec) {
    int i = blockIdx.x * blockDim.x + threadIdx.x;
    if (i < NR) dvec[i] = 1.f / (sqrtf(deg[i]) + 1e-10f);
}

// ---------------- CSR offsets (single block scan) ------------------------------
__global__ void scan_rows(const int* __restrict__ ncnt, int* __restrict__ roff,
                          int* __restrict__ cur) {
    __shared__ int part[256];
    int t = threadIdx.x;
    int base = t * 32;
    int s = 0;
    for (int i = 0; i < 32; i++) s += ncnt[base + i];
    part[t] = s;
    __syncthreads();
    if (t == 0) {
        int run = 0;
        for (int i = 0; i < 256; i++) { int v = part[i]; part[i] = run; run += v; }
        roff[NR] = run;
    }
    __syncthreads();
    int off = part[t];
    for (int i = 0; i < 32; i++) {
        roff[base + i] = off;
        cur[base + i] = off;
        off += ncnt[base + i];
    }
}

// ---------------- scatter: dense adj (scaled) + symmetric CSR (8 rows/block) ----
__global__ void scatter_adj(const int* __restrict__ kcnt, const int* __restrict__ kidx,
                            const float* __restrict__ kval, const float* __restrict__ dvec,
                            float* __restrict__ adj, int* __restrict__ cur,
                            int* __restrict__ csr_i, float* __restrict__ csr_v) {
    int row = blockIdx.x * 8 + (threadIdx.x >> 5);
    int e = threadIdx.x & 31;
    if (e < kcnt[row]) {
        int j = kidx[row * 32 + e];
        float sc = 0.5f * kval[row * 32 + e] * dvec[row] * dvec[j];
        atomicAdd(&adj[(size_t)row * NR + j], sc);
        atomicAdd(&adj[(size_t)j * NR + row], sc);
        int p = atomicAdd(&cur[row], 1);
        csr_i[p] = j;  csr_v[p] = sc;
        int q = atomicAdd(&cur[j], 1);
        csr_i[q] = row; csr_v[q] = sc;
    }
}

// ---------------- CSR SpMM ------------------------------------------------------
__global__ __launch_bounds__(256)
void spmm_csr_relu256(const int* __restrict__ roff, const int* __restrict__ ci,
                      const float* __restrict__ cv, const float* __restrict__ Y,
                      float* __restrict__ out) {
    __shared__ int   si[128];
    __shared__ float sv[128];
    int row = blockIdx.x, tid = threadIdx.x;
    int b0 = roff[row], b1 = roff[row + 1];
    float acc = 0.f;
    for (int c = b0; c < b1; c += 128) {
        int m = min(128, b1 - c);
        __syncthreads();
        if (tid < m) { si[tid] = ci[c + tid]; sv[tid] = cv[c + tid]; }
        __syncthreads();
        for (int l = 0; l < m; l++)
            acc = fmaf(sv[l], Y[(size_t)si[l] * 256 + tid], acc);
    }
    out[(size_t)row * 256 + tid] = fmaxf(acc, 0.f);
}

__global__ __launch_bounds__(256)
void spmm_csr16(const int* __restrict__ roff, const int* __restrict__ ci,
                const float* __restrict__ cv, const float* __restrict__ Y,
                float* __restrict__ out) {
    __shared__ int   si[128];
    __shared__ float sv[128];
    __shared__ float red[16][17];
    int row = blockIdx.x, tid = threadIdx.x;
    int col = tid & 15, sl = tid >> 4;
    int b0 = roff[row], b1 = roff[row + 1];
    float acc = 0.f;
    for (int c = b0; c < b1; c += 128) {
        int m = min(128, b1 - c);
        __syncthreads();
        if (tid < m) { si[tid] = ci[c + tid]; sv[tid] = cv[c + tid]; }
        __syncthreads();
        for (int l = sl; l < m; l += 16)
            acc = fmaf(sv[l], Y[(size_t)si[l] * 16 + col], acc);
    }
    red[sl][col] = acc;
    __syncthreads();
    if (sl == 0) {
        float s = 0.f;
#pragma unroll
        for (int k = 0; k < 16; k++) s += red[k][col];
        out[(size_t)row * 16 + col] = s;
    }
}

// ---------------- tiny GEMM ------------------------------------------------------
__global__ __launch_bounds__(256)
void gemm_small16(const float* __restrict__ X, const float* __restrict__ W,
                  const float* __restrict__ b, float* __restrict__ out) {
    __shared__ float Ws[16][256];
    int tid = threadIdx.x;
    int col = tid & 15, r = tid >> 4;
    for (int i = tid; i < 16 * 256; i += 256) Ws[i >> 8][i & 255] = W[i];
    __syncthreads();
    int row = blockIdx.x * 16 + r;
    const float* x = X + (size_t)row * 256;
    float acc = b[col];
    for (int k = 0; k < 256; k++) acc = fmaf(x[k], Ws[col][k], acc);
    out[(size_t)row * 16 + col] = acc;
}

// ---------------- launch -----------------------------------------------------------
extern "C" void kernel_launch(void* const* d_in, const int* in_sizes, int n_in,
                              void* d_out, int out_size) {
    (void)in_sizes; (void)n_in;
    const float* features = (const float*)d_in[0];
    const float* x        = (const float*)d_in[1];
    const float* gslW0    = (const float*)d_in[2];
    const float* gslb0    = (const float*)d_in[3];
    const float* gslW1    = (const float*)d_in[4];
    const float* gslb1    = (const float*)d_in[5];
    const float* gcnW0    = (const float*)d_in[6];
    const float* gcnb0    = (const float*)d_in[7];
    const float* gcnW1    = (const float*)d_in[8];
    const float* gcnb1    = (const float*)d_in[9];

    float *ph1, *pemb, *py0, *px1, *py1, *pdeg, *pdvec, *pfb, *pxfb, *pkval, *pcsrv;
    __nv_bfloat16 *pembB, *pS16;
    int *pkcnt, *pkidx, *pncnt, *proff, *pcur, *pcsri;
    cudaGetSymbolAddress((void**)&ph1,   g_h1);
    cudaGetSymbolAddress((void**)&pemb,  g_emb);
    cudaGetSymbolAddress((void**)&pembB, g_embB);
    cudaGetSymbolAddress((void**)&pS16,  g_S16);
    cudaGetSymbolAddress((void**)&py0,   g_y0);
    cudaGetSymbolAddress((void**)&px1,   g_x1);
    cudaGetSymbolAddress((void**)&py1,   g_y1);
    cudaGetSymbolAddress((void**)&pdeg,  g_deg);
    cudaGetSymbolAddress((void**)&pdvec, g_dvec);
    cudaGetSymbolAddress((void**)&pfb,   g_adj_fb);
    cudaGetSymbolAddress((void**)&pxfb,  g_xout_fb);
    cudaGetSymbolAddress((void**)&pkcnt, g_kcnt);
    cudaGetSymbolAddress((void**)&pkidx, g_kidx);
    cudaGetSymbolAddress((void**)&pkval, g_kval);
    cudaGetSymbolAddress((void**)&pncnt, g_ncnt);
    cudaGetSymbolAddress((void**)&proff, g_roff);
    cudaGetSymbolAddress((void**)&pcur,  g_cur);
    cudaGetSymbolAddress((void**)&pcsri, g_csr_i);
    cudaGetSymbolAddress((void**)&pcsrv, g_csr_v);

    const size_t NX = (size_t)NR * 16;
    const size_t NADJ = (size_t)NR * NR;
    float* xOut;
    float* adjOut;
    if ((size_t)out_size >= NX + NADJ) {
        xOut = (float*)d_out;
        adjOut = xOut + NX;
    } else if ((size_t)out_size == NADJ) {
        adjOut = (float*)d_out;
        xOut = pxfb;
    } else {
        xOut = (float*)d_out;
        adjOut = pfb;
    }

    // fork side stream; depends only on eFork (t=0) -> concurrent with MLP GEMMs
    cudaStream_t s2;
    cudaStreamCreateWithFlags(&s2, cudaStreamNonBlocking);
    cudaEvent_t eFork, eJoin;
    cudaEventCreateWithFlags(&eFork, cudaEventDisableTiming);
    cudaEventCreateWithFlags(&eJoin, cudaEventDisableTiming);
    cudaEventRecord(eFork, 0);
    cudaStreamWaitEvent(s2, eFork, 0);

    // issues 1-3: gsl chain
    sgemm_nt<true, true ><<<dim3(4, 64), 256>>>(features, gslW0, gslb0, ph1, NR, 512, 512);
    sgemm_nt<true, false><<<dim3(4, 64), 256>>>(ph1, gslW1, gslb1, pemb, NR, 512, 512);
    l2norm_rows_bf16<<<NR, 128>>>(pemb, (__nv_bfloat162*)pembB);

    // issue 4: S-GEMM (profiled launch)
    gemm_bf16_sym<<<dim3(64, 64), 256>>>(pembB, pS16);

    // side stream: adj zero + GCN input GEMM (independent of gsl chain)
    zero_f4<<<4096, 256, 0, s2>>>((float4*)adjOut, NADJ / 4);
    sgemm_nt<true, false><<<dim3(2, 64), 256, 0, s2>>>(x, gcnW0, gcnb0, py0, NR, 256, 512);
    cudaEventRecord(eJoin, s2);

    // selection chain
    zero_small<<<32, 256>>>(pdeg, pkcnt, pncnt);
    topk_cand<<<NR, 256>>>(pS16, pemb, pkcnt, pkidx, pkval, pdeg, pncnt);
    make_dvec<<<32, 256>>>(pdeg, pdvec);
    scan_rows<<<1, 256>>>(pncnt, proff, pcur);

    // join: scatter needs zeroed adj; spmm needs y0
    cudaStreamWaitEvent(0, eJoin, 0);
    scatter_adj<<<NR / 8, 256>>>(pkcnt, pkidx, pkval, pdvec, adjOut, pcur, pcsri, pcsrv);

    // GCN layers (CSR SpMM)
    spmm_csr_relu256<<<NR, 256>>>(proff, pcsri, pcsrv, py0, px1);
    gemm_small16<<<NR / 16, 256>>>(px1, gcnW1, gcnb1, py1);
    spmm_csr16<<<NR, 256>>>(proff, pcsri, pcsrv, py1, xOut);
}

// round 15
// speedup vs baseline: 1.0574x; 1.0294x over previous
#include <cuda_runtime.h>
#include <cuda_bf16.h>
#include <math.h>
#include <stdint.h>
#include <stddef.h>

#define NR 8192
#define KSEL 31
#define WANT_CAND 48
#define CAND_CAP 192

// ---------------- scratch ----------------------------------------------------
__device__ float g_h1[(size_t)NR * 512];
__device__ float g_emb[(size_t)NR * 512];
__device__ __align__(16) __nv_bfloat16 g_embB[(size_t)NR * 512];
__device__ __align__(16) __nv_bfloat16 g_S16[(size_t)NR * NR];  // 128 MiB bf16 sims
__device__ float g_adj_fb[(size_t)NR * NR];
__device__ float g_xout_fb[(size_t)NR * 16];
__device__ float g_y0[(size_t)NR * 256];
__device__ float g_x1[(size_t)NR * 256];
__device__ float g_y1[(size_t)NR * 16];
__device__ float g_deg[NR];
__device__ float g_dvec[NR];
__device__ int   g_kcnt[NR];
__device__ int   g_kidx[(size_t)NR * 32];
__device__ float g_kval[(size_t)NR * 32];
__device__ int   g_ncnt[NR];
__device__ int   g_roff[NR + 8];
__device__ int   g_cur[NR];
__device__ int   g_csr_i[(size_t)NR * 64];
__device__ float g_csr_v[(size_t)NR * 64];

// ---------------- utility ----------------------------------------------------
__global__ void zero_f4(float4* p, size_t n4) {
    size_t i = blockIdx.x * (size_t)blockDim.x + threadIdx.x;
    size_t st = (size_t)gridDim.x * blockDim.x;
    float4 z = make_float4(0.f, 0.f, 0.f, 0.f);
    for (; i < n4; i += st) p[i] = z;
}

__global__ void zero_small(float* __restrict__ deg, int* __restrict__ kcnt,
                           int* __restrict__ ncnt) {
    int i = blockIdx.x * blockDim.x + threadIdx.x;
    if (i < NR) { deg[i] = 0.f; kcnt[i] = 0; ncnt[i] = 0; }
}

// ---------------- fp32 SGEMM (NT), register-staged double buffering -----------
// Per-output accumulation: single sequential k-ascending fp32 FMA chain (frozen).
template <bool BIAS, bool RELU>
__global__ __launch_bounds__(256, 2)
void sgemm_nt(const float* __restrict__ A, const float* __restrict__ B,
              const float* __restrict__ bias, float* __restrict__ C,
              int M, int N, int K) {
    const int BM = 128, BN = 128, BK = 16;
    __shared__ float As[2][BK][BM];
    __shared__ float Bs[2][BK][BN];
    int tid = threadIdx.x;
    int bm = blockIdx.y * BM, bn = blockIdx.x * BN;
    int tx = tid & 15, ty = tid >> 4;
    int lr = tid >> 2;
    int lc = (tid & 3) << 2;

    float acc[8][8];
#pragma unroll
    for (int i = 0; i < 8; i++)
#pragma unroll
        for (int j = 0; j < 8; j++) acc[i][j] = 0.f;

    float4 va[2], vb[2];
#pragma unroll
    for (int h = 0; h < 2; h++) {
        int r = lr + h * 64;
        va[h] = *(const float4*)(A + (size_t)(bm + r) * K + lc);
        vb[h] = *(const float4*)(B + (size_t)(bn + r) * K + lc);
    }
#pragma unroll
    for (int h = 0; h < 2; h++) {
        int r = lr + h * 64;
        As[0][lc + 0][r] = va[h].x; As[0][lc + 1][r] = va[h].y;
        As[0][lc + 2][r] = va[h].z; As[0][lc + 3][r] = va[h].w;
        Bs[0][lc + 0][r] = vb[h].x; Bs[0][lc + 1][r] = vb[h].y;
        Bs[0][lc + 2][r] = vb[h].z; Bs[0][lc + 3][r] = vb[h].w;
    }
    __syncthreads();

    int buf = 0;
    for (int k0 = 0; k0 < K; k0 += BK) {
        bool more = (k0 + BK) < K;
        if (more) {
#pragma unroll
            for (int h = 0; h < 2; h++) {
                int r = lr + h * 64;
                va[h] = *(const float4*)(A + (size_t)(bm + r) * K + (k0 + BK + lc));
                vb[h] = *(const float4*)(B + (size_t)(bn + r) * K + (k0 + BK + lc));
            }
        }
#pragma unroll
        for (int kk = 0; kk < BK; kk++) {
            float4 a0 = *(const float4*)&As[buf][kk][ty * 8];
            float4 a1 = *(const float4*)&As[buf][kk][ty * 8 + 4];
            float4 b0 = *(const float4*)&Bs[buf][kk][tx * 8];
            float4 b1 = *(const float4*)&Bs[buf][kk][tx * 8 + 4];
            float a[8] = {a0.x, a0.y, a0.z, a0.w, a1.x, a1.y, a1.z, a1.w};
            float b[8] = {b0.x, b0.y, b0.z, b0.w, b1.x, b1.y, b1.z, b1.w};
#pragma unroll
            for (int i = 0; i < 8; i++)
#pragma unroll
                for (int j = 0; j < 8; j++) acc[i][j] = fmaf(a[i], b[j], acc[i][j]);
        }
        if (more) {
            int nb = buf ^ 1;
#pragma unroll
            for (int h = 0; h < 2; h++) {
                int r = lr + h * 64;
                As[nb][lc + 0][r] = va[h].x; As[nb][lc + 1][r] = va[h].y;
                As[nb][lc + 2][r] = va[h].z; As[nb][lc + 3][r] = va[h].w;
                Bs[nb][lc + 0][r] = vb[h].x; Bs[nb][lc + 1][r] = vb[h].y;
                Bs[nb][lc + 2][r] = vb[h].z; Bs[nb][lc + 3][r] = vb[h].w;
            }
        }
        __syncthreads();
        buf ^= 1;
    }

    float bv[8];
    if (BIAS) {
        float4 t0 = *(const float4*)(bias + bn + tx * 8);
        float4 t1 = *(const float4*)(bias + bn + tx * 8 + 4);
        bv[0] = t0.x; bv[1] = t0.y; bv[2] = t0.z; bv[3] = t0.w;
        bv[4] = t1.x; bv[5] = t1.y; bv[6] = t1.z; bv[7] = t1.w;
    }
#pragma unroll
    for (int i = 0; i < 8; i++) {
        size_t off = (size_t)(bm + ty * 8 + i) * N + bn + tx * 8;
        float v[8];
#pragma unroll
        for (int j = 0; j < 8; j++) {
            float t = acc[i][j];
            if (BIAS) t += bv[j];
            if (RELU) t = fmaxf(t, 0.f);
            v[j] = t;
        }
        *(float4*)(C + off)     = make_float4(v[0], v[1], v[2], v[3]);
        *(float4*)(C + off + 4) = make_float4(v[4], v[5], v[6], v[7]);
    }
}

// ---------------- row L2 normalize + bf16 copy ---------------------------------
__global__ void l2norm_rows_bf16(float* __restrict__ h, __nv_bfloat162* __restrict__ hb) {
    int row = blockIdx.x;
    int tid = threadIdx.x;
    float4* p = (float4*)(h + (size_t)row * 512);
    float4 v = p[tid];
    float ss = v.x * v.x + v.y * v.y + v.z * v.z + v.w * v.w;
#pragma unroll
    for (int o = 16; o; o >>= 1) ss += __shfl_xor_sync(0xFFFFFFFFu, ss, o);
    __shared__ float ws[4];
    if ((tid & 31) == 0) ws[tid >> 5] = ss;
    __syncthreads();
    float tot = ws[0] + ws[1] + ws[2] + ws[3];
    float inv = 1.f / fmaxf(sqrtf(tot), 1e-12f);
    float4 nv = make_float4(v.x * inv, v.y * inv, v.z * inv, v.w * inv);
    p[tid] = nv;
    hb[(size_t)row * 256 + 2 * tid]     = __floats2bfloat162_rn(nv.x, nv.y);
    hb[(size_t)row * 256 + 2 * tid + 1] = __floats2bfloat162_rn(nv.z, nv.w);
}

// ---------------- symmetric bf16 tensor-core GEMM: S16 = E@E^T -----------------
#define LDSM_X4(R0, R1, R2, R3, addr) \
    asm volatile("ldmatrix.sync.aligned.m8n8.x4.shared.b16 {%0,%1,%2,%3},[%4];" \
                 : "=r"(R0), "=r"(R1), "=r"(R2), "=r"(R3) : "r"(addr))

#define MMA_BF16(d, a, b) \
    asm volatile("mma.sync.aligned.m16n8k16.row.col.f32.bf16.bf16.f32 " \
                 "{%0,%1,%2,%3},{%4,%5,%6,%7},{%8,%9},{%0,%1,%2,%3};" \
                 : "+f"(d[0]), "+f"(d[1]), "+f"(d[2]), "+f"(d[3]) \
                 : "r"(a[0]), "r"(a[1]), "r"(a[2]), "r"(a[3]), "r"(b[0]), "r"(b[1]))

__device__ __forceinline__ void cp_async8(uint32_t smem, const void* gptr) {
    asm volatile("cp.async.ca.shared.global [%0], [%1], 8;\n" :: "r"(smem), "l"(gptr));
}
__device__ __forceinline__ void cp_commit() { asm volatile("cp.async.commit_group;\n" ::); }
__device__ __forceinline__ void cp_wait1()  { asm volatile("cp.async.wait_group 1;\n" ::); }

__device__ __forceinline__ void ld_stage(const __nv_bfloat16* __restrict__ E,
                                         int bm, int bn, int k0,
                                         uint32_t sA, uint32_t sB, int tid) {
#pragma unroll
    for (int q = 0; q < 4; q++) {
        int idx = tid + 256 * q;
        int r = idx >> 3;
        int c4 = (idx & 7) << 2;
        cp_async8(sA + (uint32_t)(r * 40 + c4) * 2, E + (size_t)(bm + r) * 512 + k0 + c4);
        cp_async8(sB + (uint32_t)(r * 40 + c4) * 2, E + (size_t)(bn + r) * 512 + k0 + c4);
    }
}

__global__ __launch_bounds__(256, 2)
void gemm_bf16_sym(const __nv_bfloat16* __restrict__ E, __nv_bfloat16* __restrict__ S) {
    __shared__ __align__(16) __nv_bfloat16 smf[20480];

    int bx = blockIdx.x, by = blockIdx.y;
    if (by > bx) return;                      // upper-triangular blocks only
    int tid = threadIdx.x, lane = tid & 31, w = tid >> 5;
    int wm = w & 3, wn = w >> 2;
    int bm = by * 128, bn = bx * 128;

    uint32_t base = (uint32_t)__cvta_generic_to_shared(smf);
    uint32_t baseA[2] = { base, base + 5120u * 2 };
    uint32_t baseB[2] = { base + 10240u * 2, base + 15360u * 2 };

    float acc[2][8][4];
#pragma unroll
    for (int i = 0; i < 2; i++)
#pragma unroll
        for (int j = 0; j < 8; j++)
#pragma unroll
            for (int l = 0; l < 4; l++) acc[i][j][l] = 0.f;

    ld_stage(E, bm, bn, 0, baseA[0], baseB[0], tid);
    cp_commit();

    for (int kt = 0; kt < 16; kt++) {
        if (kt < 15)
            ld_stage(E, bm, bn, (kt + 1) * 32, baseA[(kt + 1) & 1], baseB[(kt + 1) & 1], tid);
        cp_commit();
        cp_wait1();
        __syncthreads();
        int buf = kt & 1;
#pragma unroll
        for (int ks = 0; ks < 32; ks += 16) {
            uint32_t a[2][4];
#pragma unroll
            for (int mt = 0; mt < 2; mt++) {
                int r = wm * 32 + mt * 16 + (lane & 15);
                int kk = ks + ((lane >> 4) << 3);
                LDSM_X4(a[mt][0], a[mt][1], a[mt][2], a[mt][3],
                        baseA[buf] + (uint32_t)(r * 40 + kk) * 2);
            }
            uint32_t b[8][2];
#pragma unroll
            for (int p = 0; p < 4; p++) {
                int g = lane >> 3;
                int r = wn * 64 + p * 16 + ((g & 2) << 2) + (lane & 7);
                int kk = ks + ((g & 1) << 3);
                LDSM_X4(b[2 * p][0], b[2 * p][1], b[2 * p + 1][0], b[2 * p + 1][1],
                        baseB[buf] + (uint32_t)(r * 40 + kk) * 2);
            }
#pragma unroll
            for (int mt = 0; mt < 2; mt++)
#pragma unroll
                for (int nt = 0; nt < 8; nt++) MMA_BF16(acc[mt][nt], a[mt], b[nt]);
        }
        __syncthreads();
    }

    // direct store (rows bm.., cols bn..)
#pragma unroll
    for (int mt = 0; mt < 2; mt++)
#pragma unroll
        for (int nt = 0; nt < 8; nt++) {
            int row = bm + wm * 32 + mt * 16 + (lane >> 2);
            int col = bn + wn * 64 + nt * 8 + ((lane & 3) << 1);
            *(__nv_bfloat162*)(S + (size_t)row * NR + col) =
                __floats2bfloat162_rn(acc[mt][nt][0], acc[mt][nt][1]);
            *(__nv_bfloat162*)(S + (size_t)(row + 8) * NR + col) =
                __floats2bfloat162_rn(acc[mt][nt][2], acc[mt][nt][3]);
        }

    // mirrored store via smem transpose (rows bn.., cols bm..)
    if (bx != by) {
        __syncthreads();
        const int TS = 136;
#pragma unroll
        for (int mt = 0; mt < 2; mt++)
#pragma unroll
            for (int nt = 0; nt < 8; nt++) {
                int r = wm * 32 + mt * 16 + (lane >> 2);
                int c = wn * 64 + nt * 8 + ((lane & 3) << 1);
                smf[(c + 0) * TS + r]     = __float2bfloat16_rn(acc[mt][nt][0]);
                smf[(c + 1) * TS + r]     = __float2bfloat16_rn(acc[mt][nt][1]);
                smf[(c + 0) * TS + r + 8] = __float2bfloat16_rn(acc[mt][nt][2]);
                smf[(c + 1) * TS + r + 8] = __float2bfloat16_rn(acc[mt][nt][3]);
            }
        __syncthreads();
#pragma unroll
        for (int q = 0; q < 8; q++) {
            int i = tid + 256 * q;
            int r2 = i >> 4, c2 = i & 15;
            uint4 v = *(const uint4*)(smf + r2 * TS + c2 * 8);
            *(uint4*)(S + (size_t)(bn + r2) * NR + bm + c2 * 8) = v;
        }
    }
}

// ---------------- top-k: vectorized 2-pass radix + sequential rescore ----------
__device__ __forceinline__ unsigned cvt2(unsigned x) {
    unsigned lo = x & 0xFFFFu, hi = x >> 16;
    lo ^= (lo & 0x8000u) ? 0xFFFFu : 0x8000u;
    hi ^= (hi & 0x8000u) ? 0xFFFFu : 0x8000u;
    return lo | (hi << 16);
}

__global__ __launch_bounds__(256)
void topk_cand(const __nv_bfloat16* __restrict__ S, const float* __restrict__ emb,
               int* __restrict__ kcnt, int* __restrict__ kidx, float* __restrict__ kval,
               float* __restrict__ deg, int* __restrict__ ncnt) {
    __shared__ __align__(16) unsigned short keys[NR];   // 16 KB
    __shared__ unsigned whist[8][256];                   // 8 KB
    __shared__ unsigned suf[256];
    __shared__ float embrow[512];                        // 2 KB
    __shared__ int   cidx[CAND_CAP];
    __shared__ float cex[CAND_CAP];
    __shared__ unsigned sSel, sWant;
    __shared__ int cCnt;

    int row = blockIdx.x, tid = threadIdx.x, wid = tid >> 5;

    // sweep 1: vectorized key load (uint4 = 8 keys per iter, 4 iters)
    const uint4* Sr4 = (const uint4*)(S + (size_t)row * NR);
    for (int i = tid; i < NR / 8; i += 256) {
        uint4 u = Sr4[i];
        ((uint4*)keys)[i] = make_uint4(cvt2(u.x), cvt2(u.y), cvt2(u.z), cvt2(u.w));
    }
    const float4* er = (const float4*)(emb + (size_t)row * 512);
    if (tid < 128) ((float4*)embrow)[tid] = er[tid];
    if (tid == 0) cCnt = 0;

    // 2 radix passes (pairs per iteration), suffix-sum select (R12-proven)
    unsigned prefix = 0, pmask = 0, want = WANT_CAND;
#pragma unroll
    for (int pass = 1; pass >= 0; pass--) {
        for (int i = tid; i < 2048; i += 256) ((unsigned*)whist)[i] = 0;
        __syncthreads();
        int shift = pass * 8;
        for (int i = tid; i < NR / 2; i += 256) {
            unsigned pr = ((unsigned*)keys)[i];
            unsigned k0 = pr & 0xFFFFu, k1 = pr >> 16;
            if ((k0 & pmask) == prefix) atomicAdd(&whist[wid][(k0 >> shift) & 255], 1u);
            if ((k1 & pmask) == prefix) atomicAdd(&whist[wid][(k1 >> shift) & 255], 1u);
        }
        __syncthreads();
        unsigned s = 0;
#pragma unroll
        for (int wv = 0; wv < 8; wv++) s += whist[wv][tid];
        suf[tid] = s;
        __syncthreads();
#pragma unroll
        for (int off = 1; off < 256; off <<= 1) {
            unsigned add = (tid + off < 256) ? suf[tid + off] : 0u;
            __syncthreads();
            suf[tid] += add;
            __syncthreads();
        }
        {
            unsigned nxt = (tid < 255) ? suf[tid + 1] : 0u;
            if (suf[tid] >= want && nxt < want) {
                sSel = (unsigned)tid;
                sWant = want - nxt;
            }
        }
        __syncthreads();
        prefix |= sSel << shift;
        pmask |= 0xFFu << shift;
        want = sWant;
        __syncthreads();
    }
    unsigned T = prefix;

    // gather (pairs per iteration)
    for (int i = tid; i < NR / 2; i += 256) {
        unsigned pr = ((unsigned*)keys)[i];
        unsigned k0 = pr & 0xFFFFu, k1 = pr >> 16;
        if (k0 >= T) {
            int p = atomicAdd(&cCnt, 1);
            if (p < CAND_CAP) cidx[p] = 2 * i;
        }
        if (k1 >= T) {
            int p = atomicAdd(&cCnt, 1);
            if (p < CAND_CAP) cidx[p] = 2 * i + 1;
        }
    }
    __syncthreads();
    int C = min(cCnt, CAND_CAP);

    // SEQUENTIAL k-ascending fp32 FMA rescore (frozen contract)
    for (int c = tid; c < C; c += 256) {
        int j = cidx[c];
        const float4* ej = (const float4*)(emb + (size_t)j * 512);
        float s = 0.f;
        for (int q = 0; q < 128; q++) {
            float4 a = ej[q];
            s = fmaf(a.x, embrow[4 * q + 0], s);
            s = fmaf(a.y, embrow[4 * q + 1], s);
            s = fmaf(a.z, embrow[4 * q + 2], s);
            s = fmaf(a.w, embrow[4 * q + 3], s);
        }
        cex[c] = s;
    }
    __syncthreads();

    // exact top-31 (jax ties: lower index wins)
    if (tid < C) {
        float v = cex[tid];
        int ji = cidx[tid];
        int beats = 0;
        for (int j2 = 0; j2 < C; j2++) {
            float vj = cex[j2];
            beats += (vj > v) || (vj == v && cidx[j2] < ji);
        }
        if (beats < KSEL && v > 0.f) {
            int s0 = atomicAdd(&kcnt[row], 1);
            kidx[row * 32 + s0] = ji;
            kval[row * 32 + s0] = v;
            atomicAdd(&deg[row], 0.5f * v);
            atomicAdd(&deg[ji], 0.5f * v);
            atomicAdd(&ncnt[row], 1);
            atomicAdd(&ncnt[ji], 1);
        }
    }
}

// ---------------- dvec + CSR offsets (merged single-block kernel) --------------
__global__ void scan_rows(const int* __restrict__ ncnt, const float* __restrict__ deg,
                          float* __restrict__ dvec, int* __restrict__ roff,
                          int* __restrict__ cur) {
    __shared__ int part[256];
    int t = threadIdx.x;
    for (int i = t; i < NR; i += 256)
        dvec[i] = 1.f / (sqrtf(deg[i]) + 1e-10f);
    int base = t * 32;
    int s = 0;
    for (int i = 0; i < 32; i++) s += ncnt[base + i];
    part[t] = s;
    __syncthreads();
    if (t == 0) {
        int run = 0;
        for (int i = 0; i < 256; i++) { int v = part[i]; part[i] = run; run += v; }
        roff[NR] = run;
    }
    __syncthreads();
    int off = part[t];
    for (int i = 0; i < 32; i++) {
        roff[base + i] = off;
        cur[base + i] = off;
        off += ncnt[base + i];
    }
}

// ---------------- scatter: dense adj (scaled) + symmetric CSR (8 rows/block) ----
__global__ void scatter_adj(const int* __restrict__ kcnt, const int* __restrict__ kidx,
                            const float* __restrict__ kval, const float* __restrict__ dvec,
                            float* __restrict__ adj, int* __restrict__ cur,
                            int* __restrict__ csr_i, float* __restrict__ csr_v) {
    int row = blockIdx.x * 8 + (threadIdx.x >> 5);
    int e = threadIdx.x & 31;
    if (e < kcnt[row]) {
        int j = kidx[row * 32 + e];
        float sc = 0.5f * kval[row * 32 + e] * dvec[row] * dvec[j];
        atomicAdd(&adj[(size_t)row * NR + j], sc);
        atomicAdd(&adj[(size_t)j * NR + row], sc);
        int p = atomicAdd(&cur[row], 1);
        csr_i[p] = j;  csr_v[p] = sc;
        int q = atomicAdd(&cur[j], 1);
        csr_i[q] = row; csr_v[q] = sc;
    }
}

// ---------------- CSR SpMM (vectorized, no smem staging) ------------------------
__global__ __launch_bounds__(64)
void spmm_csr_relu256(const int* __restrict__ roff, const int* __restrict__ ci,
                      const float* __restrict__ cv, const float* __restrict__ Y,
                      float* __restrict__ out) {
    int row = blockIdx.x, tid = threadIdx.x;   // 64 threads x 4 cols
    int b0 = roff[row], b1 = roff[row + 1];
    float ax = 0.f, ay = 0.f, az = 0.f, aw = 0.f;
    for (int l = b0; l < b1; l++) {
        int j = __ldg(&ci[l]);
        float v = __ldg(&cv[l]);
        float4 y = *(const float4*)(Y + (size_t)j * 256 + 4 * tid);
        ax = fmaf(v, y.x, ax);
        ay = fmaf(v, y.y, ay);
        az = fmaf(v, y.z, az);
        aw = fmaf(v, y.w, aw);
    }
    *(float4*)(out + (size_t)row * 256 + 4 * tid) =
        make_float4(fmaxf(ax, 0.f), fmaxf(ay, 0.f), fmaxf(az, 0.f), fmaxf(aw, 0.f));
}

__global__ __launch_bounds__(32)
void spmm_csr16(const int* __restrict__ roff, const int* __restrict__ ci,
                const float* __restrict__ cv, const float* __restrict__ Y,
                float* __restrict__ out) {
    int row = blockIdx.x;
    int lane = threadIdx.x;
    int col = lane & 15, half = lane >> 4;
    int b0 = roff[row], b1 = roff[row + 1];
    float acc = 0.f;
    for (int l = b0 + half; l < b1; l += 2) {
        int j = __ldg(&ci[l]);
        float v = __ldg(&cv[l]);
        acc = fmaf(v, Y[(size_t)j * 16 + col], acc);
    }
    acc += __shfl_down_sync(0xFFFFFFFFu, acc, 16);
    if (half == 0) out[(size_t)row * 16 + col] = acc;
}

// ---------------- tiny GEMM ------------------------------------------------------
__global__ __launch_bounds__(256)
void gemm_small16(const float* __restrict__ X, const float* __restrict__ W,
                  const float* __restrict__ b, float* __restrict__ out) {
    __shared__ float Ws[16][256];
    int tid = threadIdx.x;
    int col = tid & 15, r = tid >> 4;
    for (int i = tid; i < 16 * 256; i += 256) Ws[i >> 8][i & 255] = W[i];
    __syncthreads();
    int row = blockIdx.x * 16 + r;
    const float* x = X + (size_t)row * 256;
    float acc = b[col];
    for (int k = 0; k < 256; k++) acc = fmaf(x[k], Ws[col][k], acc);
    out[(size_t)row * 16 + col] = acc;
}

// ---------------- launch -----------------------------------------------------------
extern "C" void kernel_launch(void* const* d_in, const int* in_sizes, int n_in,
                              void* d_out, int out_size) {
    (void)in_sizes; (void)n_in;
    const float* features = (const float*)d_in[0];
    const float* x        = (const float*)d_in[1];
    const float* gslW0    = (const float*)d_in[2];
    const float* gslb0    = (const float*)d_in[3];
    const float* gslW1    = (const float*)d_in[4];
    const float* gslb1    = (const float*)d_in[5];
    const float* gcnW0    = (const float*)d_in[6];
    const float* gcnb0    = (const float*)d_in[7];
    const float* gcnW1    = (const float*)d_in[8];
    const float* gcnb1    = (const float*)d_in[9];

    float *ph1, *pemb, *py0, *px1, *py1, *pdeg, *pdvec, *pfb, *pxfb, *pkval, *pcsrv;
    __nv_bfloat16 *pembB, *pS16;
    int *pkcnt, *pkidx, *pncnt, *proff, *pcur, *pcsri;
    cudaGetSymbolAddress((void**)&ph1,   g_h1);
    cudaGetSymbolAddress((void**)&pemb,  g_emb);
    cudaGetSymbolAddress((void**)&pembB, g_embB);
    cudaGetSymbolAddress((void**)&pS16,  g_S16);
    cudaGetSymbolAddress((void**)&py0,   g_y0);
    cudaGetSymbolAddress((void**)&px1,   g_x1);
    cudaGetSymbolAddress((void**)&py1,   g_y1);
    cudaGetSymbolAddress((void**)&pdeg,  g_deg);
    cudaGetSymbolAddress((void**)&pdvec, g_dvec);
    cudaGetSymbolAddress((void**)&pfb,   g_adj_fb);
    cudaGetSymbolAddress((void**)&pxfb,  g_xout_fb);
    cudaGetSymbolAddress((void**)&pkcnt, g_kcnt);
    cudaGetSymbolAddress((void**)&pkidx, g_kidx);
    cudaGetSymbolAddress((void**)&pkval, g_kval);
    cudaGetSymbolAddress((void**)&pncnt, g_ncnt);
    cudaGetSymbolAddress((void**)&proff, g_roff);
    cudaGetSymbolAddress((void**)&pcur,  g_cur);
    cudaGetSymbolAddress((void**)&pcsri, g_csr_i);
    cudaGetSymbolAddress((void**)&pcsrv, g_csr_v);

    const size_t NX = (size_t)NR * 16;
    const size_t NADJ = (size_t)NR * NR;
    float* xOut;
    float* adjOut;
    if ((size_t)out_size >= NX + NADJ) {
        xOut = (float*)d_out;
        adjOut = xOut + NX;
    } else if ((size_t)out_size == NADJ) {
        adjOut = (float*)d_out;
        xOut = pxfb;
    } else {
        xOut = (float*)d_out;
        adjOut = pfb;
    }

    // fork side stream; depends only on eFork (t=0) -> concurrent with MLP GEMMs
    cudaStream_t s2;
    cudaStreamCreateWithFlags(&s2, cudaStreamNonBlocking);
    cudaEvent_t eFork, eJoin;
    cudaEventCreateWithFlags(&eFork, cudaEventDisableTiming);
    cudaEventCreateWithFlags(&eJoin, cudaEventDisableTiming);
    cudaEventRecord(eFork, 0);
    cudaStreamWaitEvent(s2, eFork, 0);

    // issues 1-3: gsl chain
    sgemm_nt<true, true ><<<dim3(4, 64), 256>>>(features, gslW0, gslb0, ph1, NR, 512, 512);
    sgemm_nt<true, false><<<dim3(4, 64), 256>>>(ph1, gslW1, gslb1, pemb, NR, 512, 512);
    l2norm_rows_bf16<<<NR, 128>>>(pemb, (__nv_bfloat162*)pembB);

    // issue 4: S-GEMM (profiled launch)
    gemm_bf16_sym<<<dim3(64, 64), 256>>>(pembB, pS16);

    // side stream: adj zero + GCN input GEMM (independent of gsl chain)
    zero_f4<<<4096, 256, 0, s2>>>((float4*)adjOut, NADJ / 4);
    sgemm_nt<true, false><<<dim3(2, 64), 256, 0, s2>>>(x, gcnW0, gcnb0, py0, NR, 256, 512);
    cudaEventRecord(eJoin, s2);

    // selection chain
    zero_small<<<32, 256>>>(pdeg, pkcnt, pncnt);
    topk_cand<<<NR, 256>>>(pS16, pemb, pkcnt, pkidx, pkval, pdeg, pncnt);
    scan_rows<<<1, 256>>>(pncnt, pdeg, pdvec, proff, pcur);

    // join: scatter needs zeroed adj; spmm needs y0
    cudaStreamWaitEvent(0, eJoin, 0);
    scatter_adj<<<NR / 8, 256>>>(pkcnt, pkidx, pkval, pdvec, adjOut, pcur, pcsri, pcsrv);

    // GCN layers (vectorized CSR SpMM)
    spmm_csr_relu256<<<NR, 64>>>(proff, pcsri, pcsrv, py0, px1);
    gemm_small16<<<NR / 16, 256>>>(px1, gcnW1, gcnb1, py1);
    spmm_csr16<<<NR, 32>>>(proff, pcsri, pcsrv, py1, xOut);
}